// round 11
// baseline (speedup 1.0000x reference)
#include <cuda_runtime.h>

#define N_NODES 50000
#define N_EDGES 600000
#define F_IN 64
#define N_GRAPHS 2000
#define BN_EPS 1e-5f

#define SCAN_BT 512
#define SCAN_NB ((N_NODES + SCAN_BT - 1) / SCAN_BT)   // 98

// ---------------- scratch (device globals) ----------------------------------
__device__ float g_h[(size_t)N_NODES * 128];   // Xa (aggregated input, 64f) / spare
__device__ float g_h2[(size_t)N_NODES * 64];   // hs2 = h2 * dinv (layer2)
__device__ float g_z[(size_t)N_NODES * 128];   // pre-BN buffer
__device__ int   g_cnti[2][N_NODES];
__device__ float g_dinv[2][N_NODES];
__device__ int   g_off[2][N_NODES + 1];
__device__ int   g_head[2][N_NODES];
__device__ int   g_csrc[2][N_EDGES];
__device__ int   g_bsum[2][SCAN_NB];
__device__ float g_gcnt[N_GRAPHS];
__device__ float g_pool[N_GRAPHS * 128];
__device__ float g_cs[128], g_css[128];        // layer1 BN stats
__device__ float g_cs2[64], g_css2[64];        // layer2 BN stats
__device__ float g_mlp[N_GRAPHS * 64];
__device__ float g_ms[64], g_mss[64];

// ---------------- init + counting -------------------------------------------

__global__ void init_kernel(const int* __restrict__ batch) {
    int i = blockIdx.x * blockDim.x + threadIdx.x;
    if (i < N_GRAPHS * 128) g_pool[i] = 0.0f;
    if (i < N_GRAPHS) g_gcnt[i] = 0.0f;
    if (i < N_NODES) {
        g_cnti[0][i] = 0;
        g_cnti[1][i] = 0;
        atomicAdd(&g_gcnt[batch[i]], 1.0f);
    }
}

__global__ void count_dst_kernel(const int* __restrict__ eic, const int* __restrict__ eis) {
    int b = blockIdx.y;
    const int* dst = (b ? eis : eic) + N_EDGES;
    int i = blockIdx.x * blockDim.x + threadIdx.x;
    if (i < N_EDGES) atomicAdd(&g_cnti[b][dst[i]], 1);
}

// ---------------- 3-phase scan ----------------------------------------------

__global__ void scan_p1_kernel() {
    __shared__ int ws[SCAN_BT / 32];
    int b = blockIdx.y;
    int i = blockIdx.x * SCAN_BT + threadIdx.x;
    int lane = threadIdx.x & 31, w = threadIdx.x >> 5;
    int v = (i < N_NODES) ? g_cnti[b][i] : 0;
#pragma unroll
    for (int o = 16; o > 0; o >>= 1) v += __shfl_down_sync(~0u, v, o);
    if (lane == 0) ws[w] = v;
    __syncthreads();
    if (threadIdx.x < SCAN_BT / 32) {
        int s = ws[threadIdx.x];
#pragma unroll
        for (int o = 8; o > 0; o >>= 1) s += __shfl_down_sync(0xFFFF, s, o);
        if (threadIdx.x == 0) g_bsum[b][blockIdx.x] = s;
    }
}

__global__ void scan_p2_kernel() {
    __shared__ int sm[128];
    int b = blockIdx.x;
    int i = threadIdx.x;
    int v = (i < SCAN_NB) ? g_bsum[b][i] : 0;
    int orig = v;
    sm[i] = v;
    __syncthreads();
    for (int o = 1; o < 128; o <<= 1) {
        int t = (i >= o) ? sm[i - o] : 0;
        __syncthreads();
        sm[i] += t;
        __syncthreads();
    }
    if (i < SCAN_NB) g_bsum[b][i] = sm[i] - orig;
    if (i == 0) g_off[b][N_NODES] = N_EDGES;
}

__global__ void scan_p3_kernel() {
    __shared__ int ws[SCAN_BT / 32];
    int b = blockIdx.y;
    int i = blockIdx.x * SCAN_BT + threadIdx.x;
    int lane = threadIdx.x & 31, w = threadIdx.x >> 5;
    int c = (i < N_NODES) ? g_cnti[b][i] : 0;
    int v = c;
#pragma unroll
    for (int o = 1; o < 32; o <<= 1) {
        int t = __shfl_up_sync(~0u, v, o);
        if (lane >= o) v += t;
    }
    if (lane == 31) ws[w] = v;
    __syncthreads();
    if (w == 0 && lane < SCAN_BT / 32) {
        int s = ws[lane];
#pragma unroll
        for (int o = 1; o < SCAN_BT / 32; o <<= 1) {
            int t = __shfl_up_sync(0xFFFF, s, o);
            if (lane >= o) s += t;
        }
        ws[lane] = s;
    }
    __syncthreads();
    if (i < N_NODES) {
        int excl = g_bsum[b][blockIdx.x] + ((w > 0) ? ws[w - 1] : 0) + v - c;
        g_off[b][i] = excl;
        g_head[b][i] = excl;
        g_dinv[b][i] = rsqrtf((float)c + 1.0f);
    }
}

__global__ void scatter_kernel(const int* __restrict__ eic, const int* __restrict__ eis) {
    int b = blockIdx.y;
    const int* src = b ? eis : eic;
    const int* dst = src + N_EDGES;
    int e = blockIdx.x * blockDim.x + threadIdx.x;
    if (e < N_EDGES) {
        int slot = atomicAdd(&g_head[b][dst[e]], 1);
        g_csrc[b][slot] = src[e];
    }
}

// ---------------- agg_x: aggregate raw input (64f), write Xa -> g_h ----------
// Xa[r] = dinv[r] * ( X[r]*dinv[r] + Sum_src X[src]*dinv[src] ).
// Also zeroes layer-1 BN stat accumulators (consumed by gemm1).
__global__ void agg_x_kernel(const float* __restrict__ X, int b) {
    const int* off = g_off[b];
    const int* csrc = g_csrc[b];
    const float* dinv = g_dinv[b];
    int tid = threadIdx.x, lane = tid & 31, w = tid >> 5;
    if (blockIdx.x == 0 && tid < 128) { g_cs[tid] = 0.0f; g_css[tid] = 0.0f; }
    for (int r = blockIdx.x * 8 + w; r < N_NODES; r += gridDim.x * 8) {
        int beg = off[r], end = off[r + 1];
        float dvr = dinv[r];
        float2 x2 = *reinterpret_cast<const float2*>(&X[(size_t)r * 64 + lane * 2]);
        float acc0 = x2.x * dvr, acc1 = x2.y * dvr;
        for (int base = beg; base < end; base += 32) {
            int m = end - base; if (m > 32) m = 32;
            int idx = 0; float dvs = 0.0f;
            if (lane < m) { idx = csrc[base + lane]; dvs = dinv[idx]; }
            for (int j = 0; j < m; j++) {
                int s0 = __shfl_sync(~0u, idx, j);
                float dv = __shfl_sync(~0u, dvs, j);
                float2 a2 = *reinterpret_cast<const float2*>(&X[(size_t)s0 * 64 + lane * 2]);
                acc0 = fmaf(a2.x, dv, acc0);
                acc1 = fmaf(a2.y, dv, acc1);
            }
        }
        float2 o = make_float2(acc0 * dvr, acc1 * dvr);
        *reinterpret_cast<float2*>(&g_h[(size_t)r * 64 + lane * 2]) = o;
    }
}

// ---------------- GEMM1: z = Xa @ W1 + b1; fused BN column stats ------------
__global__ void gemm1_tiled(const float* __restrict__ W, const float* __restrict__ bias) {
    __shared__ float Xs[128][36];
    __shared__ float Wsh[32][128];
    __shared__ float scs[128], scss[128];
    int tid = threadIdx.x;
    int tx = tid & 15, ty = tid >> 4;
    int row0 = blockIdx.x * 128;
    if (tid < 128) { scs[tid] = 0.0f; scss[tid] = 0.0f; }

    float acc[8][8];
#pragma unroll
    for (int i = 0; i < 8; i++)
#pragma unroll
        for (int j = 0; j < 8; j++) acc[i][j] = 0.0f;

    for (int k0 = 0; k0 < 64; k0 += 32) {
        __syncthreads();
#pragma unroll
        for (int it = 0; it < 4; it++) {
            int idx = tid + 256 * it;
            int r = idx >> 3, c4 = (idx & 7) * 4;
            float4 x4 = make_float4(0.f, 0.f, 0.f, 0.f);
            int gr = row0 + r;
            if (gr < N_NODES)
                x4 = *reinterpret_cast<const float4*>(&g_h[(size_t)gr * 64 + k0 + c4]);
            *reinterpret_cast<float4*>(&Xs[r][c4]) = x4;
        }
#pragma unroll
        for (int it = 0; it < 4; it++) {
            int idx = tid + 256 * it;
            int r = idx >> 5, c4 = (idx & 31) * 4;
            *reinterpret_cast<float4*>(&Wsh[r][c4]) =
                *reinterpret_cast<const float4*>(&W[(size_t)(k0 + r) * 128 + c4]);
        }
        __syncthreads();
#pragma unroll 4
        for (int k = 0; k < 32; k++) {
            float av[8];
#pragma unroll
            for (int i = 0; i < 8; i++) av[i] = Xs[ty * 8 + i][k];
            float bv[8];
#pragma unroll
            for (int j = 0; j < 8; j += 4) {
                float4 w4 = *reinterpret_cast<const float4*>(&Wsh[k][tx * 8 + j]);
                bv[j] = w4.x; bv[j + 1] = w4.y; bv[j + 2] = w4.z; bv[j + 3] = w4.w;
            }
#pragma unroll
            for (int i = 0; i < 8; i++)
#pragma unroll
                for (int j = 0; j < 8; j++)
                    acc[i][j] = fmaf(av[i], bv[j], acc[i][j]);
        }
    }
    float4 b4lo = *reinterpret_cast<const float4*>(&bias[tx * 8]);
    float4 b4hi = *reinterpret_cast<const float4*>(&bias[tx * 8 + 4]);
    float bv[8] = {b4lo.x, b4lo.y, b4lo.z, b4lo.w, b4hi.x, b4hi.y, b4hi.z, b4hi.w};
    float s_loc[8], s2_loc[8];
#pragma unroll
    for (int j = 0; j < 8; j++) { s_loc[j] = 0.0f; s2_loc[j] = 0.0f; }
#pragma unroll
    for (int i = 0; i < 8; i++) {
        int r = row0 + ty * 8 + i;
        if (r >= N_NODES) continue;
        float* yr = g_z + (size_t)r * 128 + tx * 8;
        float z[8];
#pragma unroll
        for (int j = 0; j < 8; j++) {
            z[j] = acc[i][j] + bv[j];
            s_loc[j] += z[j];
            s2_loc[j] += z[j] * z[j];
        }
#pragma unroll
        for (int j = 0; j < 8; j += 4) {
            float4 v = make_float4(z[j], z[j + 1], z[j + 2], z[j + 3]);
            *reinterpret_cast<float4*>(&yr[j]) = v;
        }
    }
#pragma unroll
    for (int j = 0; j < 8; j++) {
        atomicAdd(&scs[tx * 8 + j], s_loc[j]);
        atomicAdd(&scss[tx * 8 + j], s2_loc[j]);
    }
    __syncthreads();
    if (tid < 128) {
        atomicAdd(&g_cs[tid], scs[tid]);
        atomicAdd(&g_css[tid], scss[tid]);
    }
}

// ---------------- GEMM2: hs2 = (relu(BN(z)) @ W2) * dinv; zeroes L2 stats ---
__global__ void gemm2_tiled(const float* __restrict__ W,
                            const float* __restrict__ gamma,
                            const float* __restrict__ beta, int b) {
    __shared__ float Xs[128][36];
    __shared__ float Wsh[32][64];
    __shared__ float a_s[128], b_s[128];
    int tid = threadIdx.x;
    int tx = tid & 15, ty = tid >> 4;
    int row0 = blockIdx.x * 128;
    {
        const float invN = 1.0f / (float)N_NODES;
        if (tid < 128) {
            float m = g_cs[tid] * invN;
            float v = g_css[tid] * invN - m * m;
            float a = rsqrtf(v + BN_EPS) * gamma[tid];
            a_s[tid] = a;
            b_s[tid] = beta[tid] - m * a;
        }
    }
    if (blockIdx.x == 0 && tid < 64) { g_cs2[tid] = 0.0f; g_css2[tid] = 0.0f; }

    float acc[8][4];
#pragma unroll
    for (int i = 0; i < 8; i++)
#pragma unroll
        for (int j = 0; j < 4; j++) acc[i][j] = 0.0f;

    for (int k0 = 0; k0 < 128; k0 += 32) {
        __syncthreads();
#pragma unroll
        for (int it = 0; it < 4; it++) {
            int idx = tid + 256 * it;
            int r = idx >> 3, c4 = (idx & 7) * 4;
            float4 x4 = make_float4(0.f, 0.f, 0.f, 0.f);
            int gr = row0 + r;
            if (gr < N_NODES)
                x4 = *reinterpret_cast<const float4*>(&g_z[(size_t)gr * 128 + k0 + c4]);
            x4.x = fmaxf(fmaf(x4.x, a_s[k0 + c4 + 0], b_s[k0 + c4 + 0]), 0.0f);
            x4.y = fmaxf(fmaf(x4.y, a_s[k0 + c4 + 1], b_s[k0 + c4 + 1]), 0.0f);
            x4.z = fmaxf(fmaf(x4.z, a_s[k0 + c4 + 2], b_s[k0 + c4 + 2]), 0.0f);
            x4.w = fmaxf(fmaf(x4.w, a_s[k0 + c4 + 3], b_s[k0 + c4 + 3]), 0.0f);
            *reinterpret_cast<float4*>(&Xs[r][c4]) = x4;
        }
        {
            int idx = tid;                         // 32*64/4 = 512 float4
            int r = idx >> 4, c4 = (idx & 15) * 4;
            *reinterpret_cast<float4*>(&Wsh[r][c4]) =
                *reinterpret_cast<const float4*>(&W[(size_t)(k0 + r) * 64 + c4]);
            idx = tid + 256;
            r = idx >> 4; c4 = (idx & 15) * 4;
            *reinterpret_cast<float4*>(&Wsh[r][c4]) =
                *reinterpret_cast<const float4*>(&W[(size_t)(k0 + r) * 64 + c4]);
        }
        __syncthreads();
#pragma unroll 4
        for (int k = 0; k < 32; k++) {
            float av[8];
#pragma unroll
            for (int i = 0; i < 8; i++) av[i] = Xs[ty * 8 + i][k];
            float4 w4 = *reinterpret_cast<const float4*>(&Wsh[k][tx * 4]);
            float bv[4] = {w4.x, w4.y, w4.z, w4.w};
#pragma unroll
            for (int i = 0; i < 8; i++)
#pragma unroll
                for (int j = 0; j < 4; j++)
                    acc[i][j] = fmaf(av[i], bv[j], acc[i][j]);
        }
    }
#pragma unroll
    for (int i = 0; i < 8; i++) {
        int r = row0 + ty * 8 + i;
        if (r >= N_NODES) continue;
        float dv = g_dinv[b][r];
        float4 v = make_float4(acc[i][0] * dv, acc[i][1] * dv,
                               acc[i][2] * dv, acc[i][3] * dv);
        *reinterpret_cast<float4*>(&g_h2[(size_t)r * 64 + tx * 4]) = v;
    }
}

// ---------------- layer-2 gather aggregation + BN stats ----------------------
__global__ void agg2_kernel(const float* __restrict__ bias, int b) {
    const int* off = g_off[b];
    const int* csrc = g_csrc[b];
    __shared__ float scs[8][64];
    __shared__ float scss[8][64];
    int tid = threadIdx.x, lane = tid & 31, w = tid >> 5;
    float bb0 = bias[lane * 2], bb1 = bias[lane * 2 + 1];
    float s0 = 0.0f, s1 = 0.0f, q0 = 0.0f, q1 = 0.0f;
    for (int r = blockIdx.x * 8 + w; r < N_NODES; r += gridDim.x * 8) {
        int beg = off[r], end = off[r + 1];
        float2 h2 = *reinterpret_cast<const float2*>(&g_h2[(size_t)r * 64 + lane * 2]);
        float acc0 = h2.x, acc1 = h2.y;
        for (int base = beg; base < end; base += 32) {
            int m = end - base; if (m > 32) m = 32;
            int idx = (lane < m) ? csrc[base + lane] : 0;
            for (int j = 0; j < m; j++) {
                int sn = __shfl_sync(~0u, idx, j);
                float2 a2 = *reinterpret_cast<const float2*>(&g_h2[(size_t)sn * 64 + lane * 2]);
                acc0 += a2.x; acc1 += a2.y;
            }
        }
        float dv = g_dinv[b][r];
        float z0 = fmaf(acc0, dv, bb0);
        float z1 = fmaf(acc1, dv, bb1);
        s0 += z0; q0 += z0 * z0;
        s1 += z1; q1 += z1 * z1;
        *reinterpret_cast<float2*>(&g_z[(size_t)r * 64 + lane * 2]) = make_float2(z0, z1);
    }
    scs[w][lane * 2] = s0; scs[w][lane * 2 + 1] = s1;
    scss[w][lane * 2] = q0; scss[w][lane * 2 + 1] = q1;
    __syncthreads();
    if (tid < 64) {
        float ts = 0.0f, ts2 = 0.0f;
#pragma unroll
        for (int ww = 0; ww < 8; ww++) { ts += scs[ww][tid]; ts2 += scss[ww][tid]; }
        atomicAdd(&g_cs2[tid], ts);
        atomicAdd(&g_css2[tid], ts2);
    }
}

// ---------------- BN + ReLU + segmented mean-pool (sorted batch) ------------
__global__ void bn_pool_kernel(const float* __restrict__ gamma,
                               const float* __restrict__ beta,
                               const int* __restrict__ batch, int off) {
    int c = threadIdx.x;   // 64
    const float invN = 1.0f / (float)N_NODES;
    float m = g_cs2[c] * invN;
    float a = rsqrtf(g_css2[c] * invN - m * m + BN_EPS) * gamma[c];
    float bb = beta[c] - m * a;
    const int RPB = (N_NODES + gridDim.x - 1) / gridDim.x;
    int r0 = blockIdx.x * RPB;
    int r1 = r0 + RPB; if (r1 > N_NODES) r1 = N_NODES;
    if (r0 >= r1) return;
    int cur = batch[r0];
    float acc = 0.0f;
    for (int r = r0; r < r1; r++) {
        int g = batch[r];
        if (g != cur) {
            atomicAdd(&g_pool[(size_t)cur * 128 + off + c], acc);
            acc = 0.0f; cur = g;
        }
        acc += fmaxf(fmaf(g_z[(size_t)r * 64 + c], a, bb), 0.0f);
    }
    atomicAdd(&g_pool[(size_t)cur * 128 + off + c], acc);
}

// ---------------- MLP head ---------------------------------------------------
__global__ void mlp1_kernel(const float* __restrict__ Wf1, const float* __restrict__ bf1) {
    __shared__ float p[128];
    int g = blockIdx.x;
    int j = threadIdx.x;   // 64
    if (g == 0) { g_ms[j] = 0.0f; g_mss[j] = 0.0f; }
    float cv = g_gcnt[g]; if (cv < 1.0f) cv = 1.0f;
    float inv = 1.0f / cv;
    p[j]      = g_pool[(size_t)g * 128 + j] * inv;
    p[j + 64] = g_pool[(size_t)g * 128 + 64 + j] * inv;
    __syncthreads();
    float acc = bf1[j];
    for (int k = 0; k < 128; k++) acc += p[k] * Wf1[k * 64 + j];
    g_mlp[(size_t)g * 64 + j] = acc;
}

__global__ void mlp_stats_kernel() {
    int j = threadIdx.x;   // 64
    float s = 0.0f, s2 = 0.0f;
    for (int g = blockIdx.x; g < N_GRAPHS; g += gridDim.x) {
        float v = g_mlp[(size_t)g * 64 + j];
        s += v; s2 += v * v;
    }
    atomicAdd(&g_ms[j], s);
    atomicAdd(&g_mss[j], s2);
}

__global__ void mlp2_kernel(const float* __restrict__ gf1, const float* __restrict__ bef1,
                            const float* __restrict__ Wf2, const float* __restrict__ bf2,
                            float* __restrict__ out) {
    int g = blockIdx.x * blockDim.x + threadIdx.x;
    if (g >= N_GRAPHS) return;
    const float invG = 1.0f / (float)N_GRAPHS;
    float acc = 0.0f;
#pragma unroll 8
    for (int j = 0; j < 64; j++) {
        float m = g_ms[j] * invG;
        float v = g_mss[j] * invG - m * m;
        float y = (g_mlp[(size_t)g * 64 + j] - m) * rsqrtf(v + BN_EPS) * gf1[j] + bef1[j];
        y = fmaxf(y, 0.0f);
        acc += y * Wf2[j];
    }
    out[g] = acc + bf2[0];
}

// ---------------- launch -----------------------------------------------------

extern "C" void kernel_launch(void* const* d_in, const int* in_sizes, int n_in,
                              void* d_out, int out_size) {
    const float* xc    = (const float*)d_in[0];
    const float* xs    = (const float*)d_in[1];
    const int*   eic   = (const int*)d_in[2];
    const int*   eis   = (const int*)d_in[3];
    const int*   batch = (const int*)d_in[4];

    const float* Wb[2][2]  = {{(const float*)d_in[5],  (const float*)d_in[9]},
                              {(const float*)d_in[13], (const float*)d_in[17]}};
    const float* bb[2][2]  = {{(const float*)d_in[6],  (const float*)d_in[10]},
                              {(const float*)d_in[14], (const float*)d_in[18]}};
    const float* gb[2][2]  = {{(const float*)d_in[7],  (const float*)d_in[11]},
                              {(const float*)d_in[15], (const float*)d_in[19]}};
    const float* beb[2][2] = {{(const float*)d_in[8],  (const float*)d_in[12]},
                              {(const float*)d_in[16], (const float*)d_in[20]}};
    const float* Wf1  = (const float*)d_in[21];
    const float* bf1  = (const float*)d_in[22];
    const float* gf1  = (const float*)d_in[23];
    const float* bef1 = (const float*)d_in[24];
    const float* Wf2  = (const float*)d_in[25];
    const float* bf2  = (const float*)d_in[26];
    float* out = (float*)d_out;

    const int GEMM_BLOCKS = (N_NODES + 127) / 128;   // 391

    // ---- fused CSR build for both branches ----
    init_kernel<<<(N_GRAPHS * 128 + 255) / 256, 256>>>(batch);
    count_dst_kernel<<<dim3((N_EDGES + 255) / 256, 2), 256>>>(eic, eis);
    scan_p1_kernel<<<dim3(SCAN_NB, 2), SCAN_BT>>>();
    scan_p2_kernel<<<2, 128>>>();
    scan_p3_kernel<<<dim3(SCAN_NB, 2), SCAN_BT>>>();
    scatter_kernel<<<dim3((N_EDGES + 255) / 256, 2), 256>>>(eic, eis);

    // ---- per-branch compute ----
    for (int b = 0; b < 2; b++) {
        const float* X = b ? xs : xc;
        agg_x_kernel<<<2048, 256>>>(X, b);                           // Xa -> g_h
        gemm1_tiled<<<GEMM_BLOCKS, 256>>>(Wb[b][0], bb[b][0]);       // z + L1 stats
        gemm2_tiled<<<GEMM_BLOCKS, 256>>>(Wb[b][1], gb[b][0], beb[b][0], b);
        agg2_kernel<<<2048, 256>>>(bb[b][1], b);                     // z2 + L2 stats
        bn_pool_kernel<<<1024, 64>>>(gb[b][1], beb[b][1], batch, b * 64);
    }

    mlp1_kernel<<<N_GRAPHS, 64>>>(Wf1, bf1);
    mlp_stats_kernel<<<32, 64>>>();
    mlp2_kernel<<<(N_GRAPHS + 63) / 64, 64>>>(gf1, bef1, Wf2, bf2, out);
}

// round 12
// speedup vs baseline: 1.0730x; 1.0730x over previous
#include <cuda_runtime.h>

#define N_NODES 50000
#define N_EDGES 600000
#define F_IN 64
#define N_GRAPHS 2000
#define BN_EPS 1e-5f

#define SCAN_BT 512
#define SCAN_NB ((N_NODES + SCAN_BT - 1) / SCAN_BT)   // 98

// ---------------- f32x2 packed helpers --------------------------------------
__device__ __forceinline__ unsigned long long dup_f32x2(float a) {
    unsigned long long r;
    asm("mov.b64 %0, {%1, %1};" : "=l"(r) : "r"(__float_as_uint(a)));
    return r;
}
#define FFMA2(acc, a2, b2) \
    asm("fma.rn.f32x2 %0, %1, %2, %0;" : "+l"(acc) : "l"(a2), "l"(b2))

// ---------------- scratch (device globals) ----------------------------------
__device__ float g_h[(size_t)N_NODES * 128];   // Xa (aggregated input, 64f)
__device__ float g_h2[(size_t)N_NODES * 64];   // hs2 = h2 * dinv (layer2)
__device__ float g_z[(size_t)N_NODES * 128];   // pre-BN buffer
__device__ int   g_cnti[2][N_NODES];
__device__ float g_dinv[2][N_NODES];
__device__ int   g_off[2][N_NODES + 1];
__device__ int   g_head[2][N_NODES];
__device__ int   g_csrc[2][N_EDGES];
__device__ int   g_bsum[2][SCAN_NB];
__device__ float g_gcnt[N_GRAPHS];
__device__ float g_pool[N_GRAPHS * 128];
__device__ float g_cs[128], g_css[128];        // layer1 BN stats
__device__ float g_cs2[64], g_css2[64];        // layer2 BN stats
__device__ float g_mlp[N_GRAPHS * 64];
__device__ float g_ms[64], g_mss[64];

// ---------------- init + counting -------------------------------------------

__global__ void init_kernel(const int* __restrict__ batch) {
    int i = blockIdx.x * blockDim.x + threadIdx.x;
    if (i < N_GRAPHS * 128) g_pool[i] = 0.0f;
    if (i < N_GRAPHS) g_gcnt[i] = 0.0f;
    if (i < N_NODES) {
        g_cnti[0][i] = 0;
        g_cnti[1][i] = 0;
        atomicAdd(&g_gcnt[batch[i]], 1.0f);
    }
}

__global__ void count_dst_kernel(const int* __restrict__ eic, const int* __restrict__ eis) {
    int b = blockIdx.y;
    const int* dst = (b ? eis : eic) + N_EDGES;
    int i = blockIdx.x * blockDim.x + threadIdx.x;
    if (i < N_EDGES) atomicAdd(&g_cnti[b][dst[i]], 1);
}

// ---------------- 3-phase scan ----------------------------------------------

__global__ void scan_p1_kernel() {
    __shared__ int ws[SCAN_BT / 32];
    int b = blockIdx.y;
    int i = blockIdx.x * SCAN_BT + threadIdx.x;
    int lane = threadIdx.x & 31, w = threadIdx.x >> 5;
    int v = (i < N_NODES) ? g_cnti[b][i] : 0;
#pragma unroll
    for (int o = 16; o > 0; o >>= 1) v += __shfl_down_sync(~0u, v, o);
    if (lane == 0) ws[w] = v;
    __syncthreads();
    if (threadIdx.x < SCAN_BT / 32) {
        int s = ws[threadIdx.x];
#pragma unroll
        for (int o = 8; o > 0; o >>= 1) s += __shfl_down_sync(0xFFFF, s, o);
        if (threadIdx.x == 0) g_bsum[b][blockIdx.x] = s;
    }
}

__global__ void scan_p2_kernel() {
    __shared__ int sm[128];
    int b = blockIdx.x;
    int i = threadIdx.x;
    int v = (i < SCAN_NB) ? g_bsum[b][i] : 0;
    int orig = v;
    sm[i] = v;
    __syncthreads();
    for (int o = 1; o < 128; o <<= 1) {
        int t = (i >= o) ? sm[i - o] : 0;
        __syncthreads();
        sm[i] += t;
        __syncthreads();
    }
    if (i < SCAN_NB) g_bsum[b][i] = sm[i] - orig;
    if (i == 0) g_off[b][N_NODES] = N_EDGES;
}

__global__ void scan_p3_kernel() {
    __shared__ int ws[SCAN_BT / 32];
    int b = blockIdx.y;
    int i = blockIdx.x * SCAN_BT + threadIdx.x;
    int lane = threadIdx.x & 31, w = threadIdx.x >> 5;
    int c = (i < N_NODES) ? g_cnti[b][i] : 0;
    int v = c;
#pragma unroll
    for (int o = 1; o < 32; o <<= 1) {
        int t = __shfl_up_sync(~0u, v, o);
        if (lane >= o) v += t;
    }
    if (lane == 31) ws[w] = v;
    __syncthreads();
    if (w == 0 && lane < SCAN_BT / 32) {
        int s = ws[lane];
#pragma unroll
        for (int o = 1; o < SCAN_BT / 32; o <<= 1) {
            int t = __shfl_up_sync(0xFFFF, s, o);
            if (lane >= o) s += t;
        }
        ws[lane] = s;
    }
    __syncthreads();
    if (i < N_NODES) {
        int excl = g_bsum[b][blockIdx.x] + ((w > 0) ? ws[w - 1] : 0) + v - c;
        g_off[b][i] = excl;
        g_head[b][i] = excl;
        g_dinv[b][i] = rsqrtf((float)c + 1.0f);
    }
}

__global__ void scatter_kernel(const int* __restrict__ eic, const int* __restrict__ eis) {
    int b = blockIdx.y;
    const int* src = b ? eis : eic;
    const int* dst = src + N_EDGES;
    int e = blockIdx.x * blockDim.x + threadIdx.x;
    if (e < N_EDGES) {
        int slot = atomicAdd(&g_head[b][dst[e]], 1);
        g_csrc[b][slot] = src[e];
    }
}

// ---------------- agg_x: aggregate raw input (64f), write Xa -> g_h ----------
__global__ void agg_x_kernel(const float* __restrict__ X, int b) {
    const int* off = g_off[b];
    const int* csrc = g_csrc[b];
    const float* dinv = g_dinv[b];
    int tid = threadIdx.x, lane = tid & 31, w = tid >> 5;
    if (blockIdx.x == 0 && tid < 128) { g_cs[tid] = 0.0f; g_css[tid] = 0.0f; }
    for (int r = blockIdx.x * 8 + w; r < N_NODES; r += gridDim.x * 8) {
        int beg = off[r], end = off[r + 1];
        float dvr = dinv[r];
        float2 x2 = *reinterpret_cast<const float2*>(&X[(size_t)r * 64 + lane * 2]);
        float acc0 = x2.x * dvr, acc1 = x2.y * dvr;
        for (int base = beg; base < end; base += 32) {
            int m = end - base; if (m > 32) m = 32;
            int idx = 0; float dvs = 0.0f;
            if (lane < m) { idx = csrc[base + lane]; dvs = dinv[idx]; }
            for (int j = 0; j < m; j++) {
                int s0 = __shfl_sync(~0u, idx, j);
                float dv = __shfl_sync(~0u, dvs, j);
                float2 a2 = *reinterpret_cast<const float2*>(&X[(size_t)s0 * 64 + lane * 2]);
                acc0 = fmaf(a2.x, dv, acc0);
                acc1 = fmaf(a2.y, dv, acc1);
            }
        }
        float2 o = make_float2(acc0 * dvr, acc1 * dvr);
        *reinterpret_cast<float2*>(&g_h[(size_t)r * 64 + lane * 2]) = o;
    }
}

// ---------------- GEMM1: z = Xa @ W1 + b1; fused BN stats; FFMA2 ------------
__global__ void gemm1_tiled(const float* __restrict__ W, const float* __restrict__ bias) {
    __shared__ float Xs[128][36];
    __shared__ float Wsh[32][128];
    __shared__ float scs[128], scss[128];
    int tid = threadIdx.x;
    int tx = tid & 15, ty = tid >> 4;
    int row0 = blockIdx.x * 128;
    if (tid < 128) { scs[tid] = 0.0f; scss[tid] = 0.0f; }

    unsigned long long accp[8][4];
#pragma unroll
    for (int i = 0; i < 8; i++)
#pragma unroll
        for (int jp = 0; jp < 4; jp++) accp[i][jp] = 0ULL;

    for (int k0 = 0; k0 < 64; k0 += 32) {
        __syncthreads();
#pragma unroll
        for (int it = 0; it < 4; it++) {
            int idx = tid + 256 * it;
            int r = idx >> 3, c4 = (idx & 7) * 4;
            float4 x4 = make_float4(0.f, 0.f, 0.f, 0.f);
            int gr = row0 + r;
            if (gr < N_NODES)
                x4 = *reinterpret_cast<const float4*>(&g_h[(size_t)gr * 64 + k0 + c4]);
            *reinterpret_cast<float4*>(&Xs[r][c4]) = x4;
        }
#pragma unroll
        for (int it = 0; it < 4; it++) {
            int idx = tid + 256 * it;
            int r = idx >> 5, c4 = (idx & 31) * 4;
            *reinterpret_cast<float4*>(&Wsh[r][c4]) =
                *reinterpret_cast<const float4*>(&W[(size_t)(k0 + r) * 128 + c4]);
        }
        __syncthreads();
#pragma unroll 4
        for (int k = 0; k < 32; k++) {
            unsigned long long bvp[4];
#pragma unroll
            for (int jp = 0; jp < 4; jp++)
                bvp[jp] = *reinterpret_cast<const unsigned long long*>(&Wsh[k][tx * 8 + jp * 2]);
#pragma unroll
            for (int i = 0; i < 8; i++) {
                unsigned long long a2 = dup_f32x2(Xs[ty * 8 + i][k]);
#pragma unroll
                for (int jp = 0; jp < 4; jp++) FFMA2(accp[i][jp], a2, bvp[jp]);
            }
        }
    }
    float4 b4lo = *reinterpret_cast<const float4*>(&bias[tx * 8]);
    float4 b4hi = *reinterpret_cast<const float4*>(&bias[tx * 8 + 4]);
    float bv[8] = {b4lo.x, b4lo.y, b4lo.z, b4lo.w, b4hi.x, b4hi.y, b4hi.z, b4hi.w};
    float s_loc[8], s2_loc[8];
#pragma unroll
    for (int j = 0; j < 8; j++) { s_loc[j] = 0.0f; s2_loc[j] = 0.0f; }
#pragma unroll
    for (int i = 0; i < 8; i++) {
        int r = row0 + ty * 8 + i;
        if (r >= N_NODES) continue;
        float* yr = g_z + (size_t)r * 128 + tx * 8;
        float z[8];
#pragma unroll
        for (int jp = 0; jp < 4; jp++) {
            float2 a = *reinterpret_cast<float2*>(&accp[i][jp]);
            z[jp * 2] = a.x + bv[jp * 2];
            z[jp * 2 + 1] = a.y + bv[jp * 2 + 1];
        }
#pragma unroll
        for (int j = 0; j < 8; j++) {
            s_loc[j] += z[j];
            s2_loc[j] += z[j] * z[j];
        }
#pragma unroll
        for (int j = 0; j < 8; j += 4) {
            float4 v = make_float4(z[j], z[j + 1], z[j + 2], z[j + 3]);
            *reinterpret_cast<float4*>(&yr[j]) = v;
        }
    }
#pragma unroll
    for (int j = 0; j < 8; j++) {
        atomicAdd(&scs[tx * 8 + j], s_loc[j]);
        atomicAdd(&scss[tx * 8 + j], s2_loc[j]);
    }
    __syncthreads();
    if (tid < 128) {
        atomicAdd(&g_cs[tid], scs[tid]);
        atomicAdd(&g_css[tid], scss[tid]);
    }
}

// ---------------- GEMM2: hs2 = (relu(BN(z)) @ W2) * dinv; FFMA2 -------------
__global__ void gemm2_tiled(const float* __restrict__ W,
                            const float* __restrict__ gamma,
                            const float* __restrict__ beta, int b) {
    __shared__ float Xs[128][36];
    __shared__ float Wsh[32][64];
    __shared__ float a_s[128], b_s[128];
    int tid = threadIdx.x;
    int tx = tid & 15, ty = tid >> 4;
    int row0 = blockIdx.x * 128;
    {
        const float invN = 1.0f / (float)N_NODES;
        if (tid < 128) {
            float m = g_cs[tid] * invN;
            float v = g_css[tid] * invN - m * m;
            float a = rsqrtf(v + BN_EPS) * gamma[tid];
            a_s[tid] = a;
            b_s[tid] = beta[tid] - m * a;
        }
    }
    if (blockIdx.x == 0 && tid < 64) { g_cs2[tid] = 0.0f; g_css2[tid] = 0.0f; }

    unsigned long long accp[8][2];
#pragma unroll
    for (int i = 0; i < 8; i++) { accp[i][0] = 0ULL; accp[i][1] = 0ULL; }

    for (int k0 = 0; k0 < 128; k0 += 32) {
        __syncthreads();
#pragma unroll
        for (int it = 0; it < 4; it++) {
            int idx = tid + 256 * it;
            int r = idx >> 3, c4 = (idx & 7) * 4;
            float4 x4 = make_float4(0.f, 0.f, 0.f, 0.f);
            int gr = row0 + r;
            if (gr < N_NODES)
                x4 = *reinterpret_cast<const float4*>(&g_z[(size_t)gr * 128 + k0 + c4]);
            x4.x = fmaxf(fmaf(x4.x, a_s[k0 + c4 + 0], b_s[k0 + c4 + 0]), 0.0f);
            x4.y = fmaxf(fmaf(x4.y, a_s[k0 + c4 + 1], b_s[k0 + c4 + 1]), 0.0f);
            x4.z = fmaxf(fmaf(x4.z, a_s[k0 + c4 + 2], b_s[k0 + c4 + 2]), 0.0f);
            x4.w = fmaxf(fmaf(x4.w, a_s[k0 + c4 + 3], b_s[k0 + c4 + 3]), 0.0f);
            *reinterpret_cast<float4*>(&Xs[r][c4]) = x4;
        }
        {
            int idx = tid;
            int r = idx >> 4, c4 = (idx & 15) * 4;
            *reinterpret_cast<float4*>(&Wsh[r][c4]) =
                *reinterpret_cast<const float4*>(&W[(size_t)(k0 + r) * 64 + c4]);
            idx = tid + 256;
            r = idx >> 4; c4 = (idx & 15) * 4;
            *reinterpret_cast<float4*>(&Wsh[r][c4]) =
                *reinterpret_cast<const float4*>(&W[(size_t)(k0 + r) * 64 + c4]);
        }
        __syncthreads();
#pragma unroll 4
        for (int k = 0; k < 32; k++) {
            unsigned long long bvp[2];
            bvp[0] = *reinterpret_cast<const unsigned long long*>(&Wsh[k][tx * 4]);
            bvp[1] = *reinterpret_cast<const unsigned long long*>(&Wsh[k][tx * 4 + 2]);
#pragma unroll
            for (int i = 0; i < 8; i++) {
                unsigned long long a2 = dup_f32x2(Xs[ty * 8 + i][k]);
                FFMA2(accp[i][0], a2, bvp[0]);
                FFMA2(accp[i][1], a2, bvp[1]);
            }
        }
    }
#pragma unroll
    for (int i = 0; i < 8; i++) {
        int r = row0 + ty * 8 + i;
        if (r >= N_NODES) continue;
        float dv = g_dinv[b][r];
        float2 a0 = *reinterpret_cast<float2*>(&accp[i][0]);
        float2 a1 = *reinterpret_cast<float2*>(&accp[i][1]);
        float4 v = make_float4(a0.x * dv, a0.y * dv, a1.x * dv, a1.y * dv);
        *reinterpret_cast<float4*>(&g_h2[(size_t)r * 64 + tx * 4]) = v;
    }
}

// ---------------- layer-2 gather aggregation + BN stats ----------------------
__global__ void agg2_kernel(const float* __restrict__ bias, int b) {
    const int* off = g_off[b];
    const int* csrc = g_csrc[b];
    __shared__ float scs[8][64];
    __shared__ float scss[8][64];
    int tid = threadIdx.x, lane = tid & 31, w = tid >> 5;
    float bb0 = bias[lane * 2], bb1 = bias[lane * 2 + 1];
    float s0 = 0.0f, s1 = 0.0f, q0 = 0.0f, q1 = 0.0f;
    for (int r = blockIdx.x * 8 + w; r < N_NODES; r += gridDim.x * 8) {
        int beg = off[r], end = off[r + 1];
        float2 h2 = *reinterpret_cast<const float2*>(&g_h2[(size_t)r * 64 + lane * 2]);
        float acc0 = h2.x, acc1 = h2.y;
        for (int base = beg; base < end; base += 32) {
            int m = end - base; if (m > 32) m = 32;
            int idx = (lane < m) ? csrc[base + lane] : 0;
            for (int j = 0; j < m; j++) {
                int sn = __shfl_sync(~0u, idx, j);
                float2 a2 = *reinterpret_cast<const float2*>(&g_h2[(size_t)sn * 64 + lane * 2]);
                acc0 += a2.x; acc1 += a2.y;
            }
        }
        float dv = g_dinv[b][r];
        float z0 = fmaf(acc0, dv, bb0);
        float z1 = fmaf(acc1, dv, bb1);
        s0 += z0; q0 += z0 * z0;
        s1 += z1; q1 += z1 * z1;
        *reinterpret_cast<float2*>(&g_z[(size_t)r * 64 + lane * 2]) = make_float2(z0, z1);
    }
    scs[w][lane * 2] = s0; scs[w][lane * 2 + 1] = s1;
    scss[w][lane * 2] = q0; scss[w][lane * 2 + 1] = q1;
    __syncthreads();
    if (tid < 64) {
        float ts = 0.0f, ts2 = 0.0f;
#pragma unroll
        for (int ww = 0; ww < 8; ww++) { ts += scs[ww][tid]; ts2 += scss[ww][tid]; }
        atomicAdd(&g_cs2[tid], ts);
        atomicAdd(&g_css2[tid], ts2);
    }
}

// ---------------- BN + ReLU + segmented mean-pool (sorted batch) ------------
__global__ void bn_pool_kernel(const float* __restrict__ gamma,
                               const float* __restrict__ beta,
                               const int* __restrict__ batch, int off) {
    int c = threadIdx.x;   // 64
    const float invN = 1.0f / (float)N_NODES;
    float m = g_cs2[c] * invN;
    float a = rsqrtf(g_css2[c] * invN - m * m + BN_EPS) * gamma[c];
    float bb = beta[c] - m * a;
    const int RPB = (N_NODES + gridDim.x - 1) / gridDim.x;
    int r0 = blockIdx.x * RPB;
    int r1 = r0 + RPB; if (r1 > N_NODES) r1 = N_NODES;
    if (r0 >= r1) return;
    int cur = batch[r0];
    float acc = 0.0f;
    for (int r = r0; r < r1; r++) {
        int g = batch[r];
        if (g != cur) {
            atomicAdd(&g_pool[(size_t)cur * 128 + off + c], acc);
            acc = 0.0f; cur = g;
        }
        acc += fmaxf(fmaf(g_z[(size_t)r * 64 + c], a, bb), 0.0f);
    }
    atomicAdd(&g_pool[(size_t)cur * 128 + off + c], acc);
}

// ---------------- MLP head ---------------------------------------------------
__global__ void mlp1_kernel(const float* __restrict__ Wf1, const float* __restrict__ bf1) {
    __shared__ float p[128];
    int g = blockIdx.x;
    int j = threadIdx.x;   // 64
    if (g == 0) { g_ms[j] = 0.0f; g_mss[j] = 0.0f; }
    float cv = g_gcnt[g]; if (cv < 1.0f) cv = 1.0f;
    float inv = 1.0f / cv;
    p[j]      = g_pool[(size_t)g * 128 + j] * inv;
    p[j + 64] = g_pool[(size_t)g * 128 + 64 + j] * inv;
    __syncthreads();
    float acc = bf1[j];
    for (int k = 0; k < 128; k++) acc += p[k] * Wf1[k * 64 + j];
    g_mlp[(size_t)g * 64 + j] = acc;
}

__global__ void mlp_stats_kernel() {
    int j = threadIdx.x;   // 64
    float s = 0.0f, s2 = 0.0f;
    for (int g = blockIdx.x; g < N_GRAPHS; g += gridDim.x) {
        float v = g_mlp[(size_t)g * 64 + j];
        s += v; s2 += v * v;
    }
    atomicAdd(&g_ms[j], s);
    atomicAdd(&g_mss[j], s2);
}

__global__ void mlp2_kernel(const float* __restrict__ gf1, const float* __restrict__ bef1,
                            const float* __restrict__ Wf2, const float* __restrict__ bf2,
                            float* __restrict__ out) {
    int g = blockIdx.x * blockDim.x + threadIdx.x;
    if (g >= N_GRAPHS) return;
    const float invG = 1.0f / (float)N_GRAPHS;
    float acc = 0.0f;
#pragma unroll 8
    for (int j = 0; j < 64; j++) {
        float m = g_ms[j] * invG;
        float v = g_mss[j] * invG - m * m;
        float y = (g_mlp[(size_t)g * 64 + j] - m) * rsqrtf(v + BN_EPS) * gf1[j] + bef1[j];
        y = fmaxf(y, 0.0f);
        acc += y * Wf2[j];
    }
    out[g] = acc + bf2[0];
}

// ---------------- launch -----------------------------------------------------

extern "C" void kernel_launch(void* const* d_in, const int* in_sizes, int n_in,
                              void* d_out, int out_size) {
    const float* xc    = (const float*)d_in[0];
    const float* xs    = (const float*)d_in[1];
    const int*   eic   = (const int*)d_in[2];
    const int*   eis   = (const int*)d_in[3];
    const int*   batch = (const int*)d_in[4];

    const float* Wb[2][2]  = {{(const float*)d_in[5],  (const float*)d_in[9]},
                              {(const float*)d_in[13], (const float*)d_in[17]}};
    const float* bb[2][2]  = {{(const float*)d_in[6],  (const float*)d_in[10]},
                              {(const float*)d_in[14], (const float*)d_in[18]}};
    const float* gb[2][2]  = {{(const float*)d_in[7],  (const float*)d_in[11]},
                              {(const float*)d_in[15], (const float*)d_in[19]}};
    const float* beb[2][2] = {{(const float*)d_in[8],  (const float*)d_in[12]},
                              {(const float*)d_in[16], (const float*)d_in[20]}};
    const float* Wf1  = (const float*)d_in[21];
    const float* bf1  = (const float*)d_in[22];
    const float* gf1  = (const float*)d_in[23];
    const float* bef1 = (const float*)d_in[24];
    const float* Wf2  = (const float*)d_in[25];
    const float* bf2  = (const float*)d_in[26];
    float* out = (float*)d_out;

    const int GEMM_BLOCKS = (N_NODES + 127) / 128;   // 391

    // ---- fused CSR build for both branches ----
    init_kernel<<<(N_GRAPHS * 128 + 255) / 256, 256>>>(batch);
    count_dst_kernel<<<dim3((N_EDGES + 255) / 256, 2), 256>>>(eic, eis);
    scan_p1_kernel<<<dim3(SCAN_NB, 2), SCAN_BT>>>();
    scan_p2_kernel<<<2, 128>>>();
    scan_p3_kernel<<<dim3(SCAN_NB, 2), SCAN_BT>>>();
    scatter_kernel<<<dim3((N_EDGES + 255) / 256, 2), 256>>>(eic, eis);

    // ---- per-branch compute ----
    for (int b = 0; b < 2; b++) {
        const float* X = b ? xs : xc;
        agg_x_kernel<<<2048, 256>>>(X, b);                           // Xa -> g_h
        gemm1_tiled<<<GEMM_BLOCKS, 256>>>(Wb[b][0], bb[b][0]);       // z + L1 stats
        gemm2_tiled<<<GEMM_BLOCKS, 256>>>(Wb[b][1], gb[b][0], beb[b][0], b);
        agg2_kernel<<<2048, 256>>>(bb[b][1], b);                     // z2 + L2 stats
        bn_pool_kernel<<<1024, 64>>>(gb[b][1], beb[b][1], batch, b * 64);
    }

    mlp1_kernel<<<N_GRAPHS, 64>>>(Wf1, bf1);
    mlp_stats_kernel<<<32, 64>>>();
    mlp2_kernel<<<(N_GRAPHS + 63) / 64, 64>>>(gf1, bef1, Wf2, bf2, out);
}

// round 14
// speedup vs baseline: 1.0866x; 1.0127x over previous
#include <cuda_runtime.h>

#define N_NODES 50000
#define N_EDGES 600000
#define F_IN 64
#define N_GRAPHS 2000
#define BN_EPS 1e-5f

#define SCAN_BT 512
#define SCAN_NB ((N_NODES + SCAN_BT - 1) / SCAN_BT)   // 98

// ---------------- f32x2 packed helpers --------------------------------------
__device__ __forceinline__ unsigned long long dup_f32x2(float a) {
    unsigned long long r;
    asm("mov.b64 %0, {%1, %1};" : "=l"(r) : "r"(__float_as_uint(a)));
    return r;
}
#define FFMA2(acc, a2, b2) \
    asm("fma.rn.f32x2 %0, %1, %2, %0;" : "+l"(acc) : "l"(a2), "l"(b2))

// ---------------- scratch (device globals) ----------------------------------
__device__ float g_h[(size_t)N_NODES * 128];   // Xa (aggregated input, 64f)
__device__ float g_h2[(size_t)N_NODES * 64];   // hs2 = h2 * dinv (layer2)
__device__ float g_z[(size_t)N_NODES * 128];   // pre-BN buffer
__device__ int   g_cnti[2][N_NODES];
__device__ float g_dinv[2][N_NODES];
__device__ int   g_off[2][N_NODES + 1];
__device__ int   g_head[2][N_NODES];
__device__ int   g_csrc[2][N_EDGES];
__device__ int   g_bsum[2][SCAN_NB];
__device__ float g_gcnt[N_GRAPHS];
__device__ float g_pool[N_GRAPHS * 128];
__device__ float g_cs[128], g_css[128];        // layer1 BN stats
__device__ float g_cs2[64], g_css2[64];        // layer2 BN stats
__device__ float g_mlp[N_GRAPHS * 64];
__device__ float g_ms[64], g_mss[64];

// ---------------- init + counting -------------------------------------------

__global__ void init_kernel(const int* __restrict__ batch) {
    int i = blockIdx.x * blockDim.x + threadIdx.x;
    if (i < N_GRAPHS * 128) g_pool[i] = 0.0f;
    if (i < N_GRAPHS) g_gcnt[i] = 0.0f;
    if (i < N_NODES) {
        g_cnti[0][i] = 0;
        g_cnti[1][i] = 0;
        atomicAdd(&g_gcnt[batch[i]], 1.0f);
    }
}

__global__ void count_dst_kernel(const int* __restrict__ eic, const int* __restrict__ eis) {
    int b = blockIdx.y;
    const int* dst = (b ? eis : eic) + N_EDGES;
    int i = blockIdx.x * blockDim.x + threadIdx.x;
    if (i < N_EDGES) atomicAdd(&g_cnti[b][dst[i]], 1);
}

// ---------------- 3-phase scan ----------------------------------------------

__global__ void scan_p1_kernel() {
    __shared__ int ws[SCAN_BT / 32];
    int b = blockIdx.y;
    int i = blockIdx.x * SCAN_BT + threadIdx.x;
    int lane = threadIdx.x & 31, w = threadIdx.x >> 5;
    int v = (i < N_NODES) ? g_cnti[b][i] : 0;
#pragma unroll
    for (int o = 16; o > 0; o >>= 1) v += __shfl_down_sync(~0u, v, o);
    if (lane == 0) ws[w] = v;
    __syncthreads();
    if (threadIdx.x < SCAN_BT / 32) {
        int s = ws[threadIdx.x];
#pragma unroll
        for (int o = 8; o > 0; o >>= 1) s += __shfl_down_sync(0xFFFF, s, o);
        if (threadIdx.x == 0) g_bsum[b][blockIdx.x] = s;
    }
}

__global__ void scan_p2_kernel() {
    __shared__ int sm[128];
    int b = blockIdx.x;
    int i = threadIdx.x;
    int v = (i < SCAN_NB) ? g_bsum[b][i] : 0;
    int orig = v;
    sm[i] = v;
    __syncthreads();
    for (int o = 1; o < 128; o <<= 1) {
        int t = (i >= o) ? sm[i - o] : 0;
        __syncthreads();
        sm[i] += t;
        __syncthreads();
    }
    if (i < SCAN_NB) g_bsum[b][i] = sm[i] - orig;
    if (i == 0) g_off[b][N_NODES] = N_EDGES;
}

__global__ void scan_p3_kernel() {
    __shared__ int ws[SCAN_BT / 32];
    int b = blockIdx.y;
    int i = blockIdx.x * SCAN_BT + threadIdx.x;
    int lane = threadIdx.x & 31, w = threadIdx.x >> 5;
    int c = (i < N_NODES) ? g_cnti[b][i] : 0;
    int v = c;
#pragma unroll
    for (int o = 1; o < 32; o <<= 1) {
        int t = __shfl_up_sync(~0u, v, o);
        if (lane >= o) v += t;
    }
    if (lane == 31) ws[w] = v;
    __syncthreads();
    if (w == 0 && lane < SCAN_BT / 32) {
        int s = ws[lane];
#pragma unroll
        for (int o = 1; o < SCAN_BT / 32; o <<= 1) {
            int t = __shfl_up_sync(0xFFFF, s, o);
            if (lane >= o) s += t;
        }
        ws[lane] = s;
    }
    __syncthreads();
    if (i < N_NODES) {
        int excl = g_bsum[b][blockIdx.x] + ((w > 0) ? ws[w - 1] : 0) + v - c;
        g_off[b][i] = excl;
        g_head[b][i] = excl;
        g_dinv[b][i] = rsqrtf((float)c + 1.0f);
    }
}

__global__ void scatter_kernel(const int* __restrict__ eic, const int* __restrict__ eis) {
    int b = blockIdx.y;
    const int* src = b ? eis : eic;
    const int* dst = src + N_EDGES;
    int e = blockIdx.x * blockDim.x + threadIdx.x;
    if (e < N_EDGES) {
        int slot = atomicAdd(&g_head[b][dst[e]], 1);
        g_csrc[b][slot] = src[e];
    }
}

// ---------------- agg_x: aggregate raw input (64f), write Xa -> g_h ----------
// 4-way unrolled gather, dual accumulator pairs for MLP.
__global__ void agg_x_kernel(const float* __restrict__ X, int b) {
    const int* off = g_off[b];
    const int* csrc = g_csrc[b];
    const float* dinv = g_dinv[b];
    int tid = threadIdx.x, lane = tid & 31, w = tid >> 5;
    if (blockIdx.x == 0 && tid < 128) { g_cs[tid] = 0.0f; g_css[tid] = 0.0f; }
    for (int r = blockIdx.x * 8 + w; r < N_NODES; r += gridDim.x * 8) {
        int beg = off[r], end = off[r + 1];
        float dvr = dinv[r];
        float2 x2 = *reinterpret_cast<const float2*>(&X[(size_t)r * 64 + lane * 2]);
        float accA0 = x2.x * dvr, accA1 = x2.y * dvr;
        float accB0 = 0.0f, accB1 = 0.0f;
        for (int base = beg; base < end; base += 32) {
            int m = end - base; if (m > 32) m = 32;
            int idx = 0; float dvs = 0.0f;
            if (lane < m) { idx = csrc[base + lane]; dvs = dinv[idx]; }
            int jj = 0;
            for (; jj + 4 <= m; jj += 4) {
                int s0 = __shfl_sync(~0u, idx, jj);
                int s1 = __shfl_sync(~0u, idx, jj + 1);
                int s2 = __shfl_sync(~0u, idx, jj + 2);
                int s3 = __shfl_sync(~0u, idx, jj + 3);
                float d0 = __shfl_sync(~0u, dvs, jj);
                float d1 = __shfl_sync(~0u, dvs, jj + 1);
                float d2 = __shfl_sync(~0u, dvs, jj + 2);
                float d3 = __shfl_sync(~0u, dvs, jj + 3);
                float2 a0 = *reinterpret_cast<const float2*>(&X[(size_t)s0 * 64 + lane * 2]);
                float2 a1 = *reinterpret_cast<const float2*>(&X[(size_t)s1 * 64 + lane * 2]);
                float2 a2 = *reinterpret_cast<const float2*>(&X[(size_t)s2 * 64 + lane * 2]);
                float2 a3 = *reinterpret_cast<const float2*>(&X[(size_t)s3 * 64 + lane * 2]);
                accA0 = fmaf(a0.x, d0, accA0); accA1 = fmaf(a0.y, d0, accA1);
                accB0 = fmaf(a1.x, d1, accB0); accB1 = fmaf(a1.y, d1, accB1);
                accA0 = fmaf(a2.x, d2, accA0); accA1 = fmaf(a2.y, d2, accA1);
                accB0 = fmaf(a3.x, d3, accB0); accB1 = fmaf(a3.y, d3, accB1);
            }
            for (; jj < m; jj++) {
                int s0 = __shfl_sync(~0u, idx, jj);
                float d0 = __shfl_sync(~0u, dvs, jj);
                float2 a0 = *reinterpret_cast<const float2*>(&X[(size_t)s0 * 64 + lane * 2]);
                accA0 = fmaf(a0.x, d0, accA0); accA1 = fmaf(a0.y, d0, accA1);
            }
        }
        float2 o = make_float2((accA0 + accB0) * dvr, (accA1 + accB1) * dvr);
        *reinterpret_cast<float2*>(&g_h[(size_t)r * 64 + lane * 2]) = o;
    }
}

// ---------------- GEMM1: z = Xa @ W1 + b1; fused BN stats; FFMA2 ------------
__global__ void gemm1_tiled(const float* __restrict__ W, const float* __restrict__ bias) {
    __shared__ float Xs[128][36];
    __shared__ float Wsh[32][128];
    __shared__ float scs[128], scss[128];
    int tid = threadIdx.x;
    int tx = tid & 15, ty = tid >> 4;
    int row0 = blockIdx.x * 128;
    if (tid < 128) { scs[tid] = 0.0f; scss[tid] = 0.0f; }

    unsigned long long accp[8][4];
#pragma unroll
    for (int i = 0; i < 8; i++)
#pragma unroll
        for (int jp = 0; jp < 4; jp++) accp[i][jp] = 0ULL;

    for (int k0 = 0; k0 < 64; k0 += 32) {
        __syncthreads();
#pragma unroll
        for (int it = 0; it < 4; it++) {
            int idx = tid + 256 * it;
            int r = idx >> 3, c4 = (idx & 7) * 4;
            float4 x4 = make_float4(0.f, 0.f, 0.f, 0.f);
            int gr = row0 + r;
            if (gr < N_NODES)
                x4 = *reinterpret_cast<const float4*>(&g_h[(size_t)gr * 64 + k0 + c4]);
            *reinterpret_cast<float4*>(&Xs[r][c4]) = x4;
        }
#pragma unroll
        for (int it = 0; it < 4; it++) {
            int idx = tid + 256 * it;
            int r = idx >> 5, c4 = (idx & 31) * 4;
            *reinterpret_cast<float4*>(&Wsh[r][c4]) =
                *reinterpret_cast<const float4*>(&W[(size_t)(k0 + r) * 128 + c4]);
        }
        __syncthreads();
#pragma unroll 4
        for (int k = 0; k < 32; k++) {
            unsigned long long bvp[4];
#pragma unroll
            for (int jp = 0; jp < 4; jp++)
                bvp[jp] = *reinterpret_cast<const unsigned long long*>(&Wsh[k][tx * 8 + jp * 2]);
#pragma unroll
            for (int i = 0; i < 8; i++) {
                unsigned long long a2 = dup_f32x2(Xs[ty * 8 + i][k]);
#pragma unroll
                for (int jp = 0; jp < 4; jp++) FFMA2(accp[i][jp], a2, bvp[jp]);
            }
        }
    }
    float4 b4lo = *reinterpret_cast<const float4*>(&bias[tx * 8]);
    float4 b4hi = *reinterpret_cast<const float4*>(&bias[tx * 8 + 4]);
    float bv[8] = {b4lo.x, b4lo.y, b4lo.z, b4lo.w, b4hi.x, b4hi.y, b4hi.z, b4hi.w};
    float s_loc[8], s2_loc[8];
#pragma unroll
    for (int j = 0; j < 8; j++) { s_loc[j] = 0.0f; s2_loc[j] = 0.0f; }
#pragma unroll
    for (int i = 0; i < 8; i++) {
        int r = row0 + ty * 8 + i;
        if (r >= N_NODES) continue;
        float* yr = g_z + (size_t)r * 128 + tx * 8;
        float z[8];
#pragma unroll
        for (int jp = 0; jp < 4; jp++) {
            float2 a = *reinterpret_cast<float2*>(&accp[i][jp]);
            z[jp * 2] = a.x + bv[jp * 2];
            z[jp * 2 + 1] = a.y + bv[jp * 2 + 1];
        }
#pragma unroll
        for (int j = 0; j < 8; j++) {
            s_loc[j] += z[j];
            s2_loc[j] += z[j] * z[j];
        }
#pragma unroll
        for (int j = 0; j < 8; j += 4) {
            float4 v = make_float4(z[j], z[j + 1], z[j + 2], z[j + 3]);
            *reinterpret_cast<float4*>(&yr[j]) = v;
        }
    }
#pragma unroll
    for (int j = 0; j < 8; j++) {
        atomicAdd(&scs[tx * 8 + j], s_loc[j]);
        atomicAdd(&scss[tx * 8 + j], s2_loc[j]);
    }
    __syncthreads();
    if (tid < 128) {
        atomicAdd(&g_cs[tid], scs[tid]);
        atomicAdd(&g_css[tid], scss[tid]);
    }
}

// ---------------- GEMM2: hs2 = (relu(BN(z)) @ W2) * dinv; FFMA2 -------------
__global__ void gemm2_tiled(const float* __restrict__ W,
                            const float* __restrict__ gamma,
                            const float* __restrict__ beta, int b) {
    __shared__ float Xs[128][36];
    __shared__ float Wsh[32][64];
    __shared__ float a_s[128], b_s[128];
    int tid = threadIdx.x;
    int tx = tid & 15, ty = tid >> 4;
    int row0 = blockIdx.x * 128;
    {
        const float invN = 1.0f / (float)N_NODES;
        if (tid < 128) {
            float m = g_cs[tid] * invN;
            float v = g_css[tid] * invN - m * m;
            float a = rsqrtf(v + BN_EPS) * gamma[tid];
            a_s[tid] = a;
            b_s[tid] = beta[tid] - m * a;
        }
    }
    if (blockIdx.x == 0 && tid < 64) { g_cs2[tid] = 0.0f; g_css2[tid] = 0.0f; }

    unsigned long long accp[8][2];
#pragma unroll
    for (int i = 0; i < 8; i++) { accp[i][0] = 0ULL; accp[i][1] = 0ULL; }

    for (int k0 = 0; k0 < 128; k0 += 32) {
        __syncthreads();
#pragma unroll
        for (int it = 0; it < 4; it++) {
            int idx = tid + 256 * it;
            int r = idx >> 3, c4 = (idx & 7) * 4;
            float4 x4 = make_float4(0.f, 0.f, 0.f, 0.f);
            int gr = row0 + r;
            if (gr < N_NODES)
                x4 = *reinterpret_cast<const float4*>(&g_z[(size_t)gr * 128 + k0 + c4]);
            x4.x = fmaxf(fmaf(x4.x, a_s[k0 + c4 + 0], b_s[k0 + c4 + 0]), 0.0f);
            x4.y = fmaxf(fmaf(x4.y, a_s[k0 + c4 + 1], b_s[k0 + c4 + 1]), 0.0f);
            x4.z = fmaxf(fmaf(x4.z, a_s[k0 + c4 + 2], b_s[k0 + c4 + 2]), 0.0f);
            x4.w = fmaxf(fmaf(x4.w, a_s[k0 + c4 + 3], b_s[k0 + c4 + 3]), 0.0f);
            *reinterpret_cast<float4*>(&Xs[r][c4]) = x4;
        }
        {
            int idx = tid;
            int r = idx >> 4, c4 = (idx & 15) * 4;
            *reinterpret_cast<float4*>(&Wsh[r][c4]) =
                *reinterpret_cast<const float4*>(&W[(size_t)(k0 + r) * 64 + c4]);
            idx = tid + 256;
            r = idx >> 4; c4 = (idx & 15) * 4;
            *reinterpret_cast<float4*>(&Wsh[r][c4]) =
                *reinterpret_cast<const float4*>(&W[(size_t)(k0 + r) * 64 + c4]);
        }
        __syncthreads();
#pragma unroll 4
        for (int k = 0; k < 32; k++) {
            unsigned long long bvp[2];
            bvp[0] = *reinterpret_cast<const unsigned long long*>(&Wsh[k][tx * 4]);
            bvp[1] = *reinterpret_cast<const unsigned long long*>(&Wsh[k][tx * 4 + 2]);
#pragma unroll
            for (int i = 0; i < 8; i++) {
                unsigned long long a2 = dup_f32x2(Xs[ty * 8 + i][k]);
                FFMA2(accp[i][0], a2, bvp[0]);
                FFMA2(accp[i][1], a2, bvp[1]);
            }
        }
    }
#pragma unroll
    for (int i = 0; i < 8; i++) {
        int r = row0 + ty * 8 + i;
        if (r >= N_NODES) continue;
        float dv = g_dinv[b][r];
        float2 a0 = *reinterpret_cast<float2*>(&accp[i][0]);
        float2 a1 = *reinterpret_cast<float2*>(&accp[i][1]);
        float4 v = make_float4(a0.x * dv, a0.y * dv, a1.x * dv, a1.y * dv);
        *reinterpret_cast<float4*>(&g_h2[(size_t)r * 64 + tx * 4]) = v;
    }
}

// ---------------- layer-2 gather aggregation + BN stats ----------------------
// 4-way unrolled gather, dual accumulator pairs.
__global__ void agg2_kernel(const float* __restrict__ bias, int b) {
    const int* off = g_off[b];
    const int* csrc = g_csrc[b];
    __shared__ float scs[8][64];
    __shared__ float scss[8][64];
    int tid = threadIdx.x, lane = tid & 31, w = tid >> 5;
    float bb0 = bias[lane * 2], bb1 = bias[lane * 2 + 1];
    float s0 = 0.0f, s1 = 0.0f, q0 = 0.0f, q1 = 0.0f;
    for (int r = blockIdx.x * 8 + w; r < N_NODES; r += gridDim.x * 8) {
        int beg = off[r], end = off[r + 1];
        float2 h2 = *reinterpret_cast<const float2*>(&g_h2[(size_t)r * 64 + lane * 2]);
        float accA0 = h2.x, accA1 = h2.y;
        float accB0 = 0.0f, accB1 = 0.0f;
        for (int base = beg; base < end; base += 32) {
            int m = end - base; if (m > 32) m = 32;
            int idx = (lane < m) ? csrc[base + lane] : 0;
            int jj = 0;
            for (; jj + 4 <= m; jj += 4) {
                int s0i = __shfl_sync(~0u, idx, jj);
                int s1i = __shfl_sync(~0u, idx, jj + 1);
                int s2i = __shfl_sync(~0u, idx, jj + 2);
                int s3i = __shfl_sync(~0u, idx, jj + 3);
                float2 a0 = *reinterpret_cast<const float2*>(&g_h2[(size_t)s0i * 64 + lane * 2]);
                float2 a1 = *reinterpret_cast<const float2*>(&g_h2[(size_t)s1i * 64 + lane * 2]);
                float2 a2 = *reinterpret_cast<const float2*>(&g_h2[(size_t)s2i * 64 + lane * 2]);
                float2 a3 = *reinterpret_cast<const float2*>(&g_h2[(size_t)s3i * 64 + lane * 2]);
                accA0 += a0.x + a2.x; accA1 += a0.y + a2.y;
                accB0 += a1.x + a3.x; accB1 += a1.y + a3.y;
            }
            for (; jj < m; jj++) {
                int s0i = __shfl_sync(~0u, idx, jj);
                float2 a0 = *reinterpret_cast<const float2*>(&g_h2[(size_t)s0i * 64 + lane * 2]);
                accA0 += a0.x; accA1 += a0.y;
            }
        }
        float dv = g_dinv[b][r];
        float z0 = fmaf(accA0 + accB0, dv, bb0);
        float z1 = fmaf(accA1 + accB1, dv, bb1);
        s0 += z0; q0 += z0 * z0;
        s1 += z1; q1 += z1 * z1;
        *reinterpret_cast<float2*>(&g_z[(size_t)r * 64 + lane * 2]) = make_float2(z0, z1);
    }
    scs[w][lane * 2] = s0; scs[w][lane * 2 + 1] = s1;
    scss[w][lane * 2] = q0; scss[w][lane * 2 + 1] = q1;
    __syncthreads();
    if (tid < 64) {
        float ts = 0.0f, ts2 = 0.0f;
#pragma unroll
        for (int ww = 0; ww < 8; ww++) { ts += scs[ww][tid]; ts2 += scss[ww][tid]; }
        atomicAdd(&g_cs2[tid], ts);
        atomicAdd(&g_css2[tid], ts2);
    }
}

// ---------------- BN + ReLU + segmented mean-pool (sorted batch) ------------
__global__ void bn_pool_kernel(const float* __restrict__ gamma,
                               const float* __restrict__ beta,
                               const int* __restrict__ batch, int off) {
    int c = threadIdx.x;   // 64
    const float invN = 1.0f / (float)N_NODES;
    float m = g_cs2[c] * invN;
    float a = rsqrtf(g_css2[c] * invN - m * m + BN_EPS) * gamma[c];
    float bb = beta[c] - m * a;
    const int RPB = (N_NODES + gridDim.x - 1) / gridDim.x;
    int r0 = blockIdx.x * RPB;
    int r1 = r0 + RPB; if (r1 > N_NODES) r1 = N_NODES;
    if (r0 >= r1) return;
    int cur = batch[r0];
    float acc = 0.0f;
    for (int r = r0; r < r1; r++) {
        int g = batch[r];
        if (g != cur) {
            atomicAdd(&g_pool[(size_t)cur * 128 + off + c], acc);
            acc = 0.0f; cur = g;
        }
        acc += fmaxf(fmaf(g_z[(size_t)r * 64 + c], a, bb), 0.0f);
    }
    atomicAdd(&g_pool[(size_t)cur * 128 + off + c], acc);
}

// ---------------- MLP head ---------------------------------------------------
__global__ void mlp1_kernel(const float* __restrict__ Wf1, const float* __restrict__ bf1) {
    __shared__ float p[128];
    int g = blockIdx.x;
    int j = threadIdx.x;   // 64
    if (g == 0) { g_ms[j] = 0.0f; g_mss[j] = 0.0f; }
    float cv = g_gcnt[g]; if (cv < 1.0f) cv = 1.0f;
    float inv = 1.0f / cv;
    p[j]      = g_pool[(size_t)g * 128 + j] * inv;
    p[j + 64] = g_pool[(size_t)g * 128 + 64 + j] * inv;
    __syncthreads();
    float acc = bf1[j];
    for (int k = 0; k < 128; k++) acc += p[k] * Wf1[k * 64 + j];
    g_mlp[(size_t)g * 64 + j] = acc;
}

__global__ void mlp_stats_kernel() {
    int j = threadIdx.x;   // 64
    float s = 0.0f, s2 = 0.0f;
    for (int g = blockIdx.x; g < N_GRAPHS; g += gridDim.x) {
        float v = g_mlp[(size_t)g * 64 + j];
        s += v; s2 += v * v;
    }
    atomicAdd(&g_ms[j], s);
    atomicAdd(&g_mss[j], s2);
}

__global__ void mlp2_kernel(const float* __restrict__ gf1, const float* __restrict__ bef1,
                            const float* __restrict__ Wf2, const float* __restrict__ bf2,
                            float* __restrict__ out) {
    int g = blockIdx.x * blockDim.x + threadIdx.x;
    if (g >= N_GRAPHS) return;
    const float invG = 1.0f / (float)N_GRAPHS;
    float acc = 0.0f;
#pragma unroll 8
    for (int j = 0; j < 64; j++) {
        float m = g_ms[j] * invG;
        float v = g_mss[j] * invG - m * m;
        float y = (g_mlp[(size_t)g * 64 + j] - m) * rsqrtf(v + BN_EPS) * gf1[j] + bef1[j];
        y = fmaxf(y, 0.0f);
        acc += y * Wf2[j];
    }
    out[g] = acc + bf2[0];
}

// ---------------- launch -----------------------------------------------------

extern "C" void kernel_launch(void* const* d_in, const int* in_sizes, int n_in,
                              void* d_out, int out_size) {
    const float* xc    = (const float*)d_in[0];
    const float* xs    = (const float*)d_in[1];
    const int*   eic   = (const int*)d_in[2];
    const int*   eis   = (const int*)d_in[3];
    const int*   batch = (const int*)d_in[4];

    const float* Wb[2][2]  = {{(const float*)d_in[5],  (const float*)d_in[9]},
                              {(const float*)d_in[13], (const float*)d_in[17]}};
    const float* bb[2][2]  = {{(const float*)d_in[6],  (const float*)d_in[10]},
                              {(const float*)d_in[14], (const float*)d_in[18]}};
    const float* gb[2][2]  = {{(const float*)d_in[7],  (const float*)d_in[11]},
                              {(const float*)d_in[15], (const float*)d_in[19]}};
    const float* beb[2][2] = {{(const float*)d_in[8],  (const float*)d_in[12]},
                              {(const float*)d_in[16], (const float*)d_in[20]}};
    const float* Wf1  = (const float*)d_in[21];
    const float* bf1  = (const float*)d_in[22];
    const float* gf1  = (const float*)d_in[23];
    const float* bef1 = (const float*)d_in[24];
    const float* Wf2  = (const float*)d_in[25];
    const float* bf2  = (const float*)d_in[26];
    float* out = (float*)d_out;

    const int GEMM_BLOCKS = (N_NODES + 127) / 128;   // 391

    // ---- fused CSR build for both branches ----
    init_kernel<<<(N_GRAPHS * 128 + 255) / 256, 256>>>(batch);
    count_dst_kernel<<<dim3((N_EDGES + 255) / 256, 2), 256>>>(eic, eis);
    scan_p1_kernel<<<dim3(SCAN_NB, 2), SCAN_BT>>>();
    scan_p2_kernel<<<2, 128>>>();
    scan_p3_kernel<<<dim3(SCAN_NB, 2), SCAN_BT>>>();
    scatter_kernel<<<dim3((N_EDGES + 255) / 256, 2), 256>>>(eic, eis);

    // ---- per-branch compute ----
    for (int b = 0; b < 2; b++) {
        const float* X = b ? xs : xc;
        agg_x_kernel<<<2048, 256>>>(X, b);                           // Xa -> g_h
        gemm1_tiled<<<GEMM_BLOCKS, 256>>>(Wb[b][0], bb[b][0]);       // z + L1 stats
        gemm2_tiled<<<GEMM_BLOCKS, 256>>>(Wb[b][1], gb[b][0], beb[b][0], b);
        agg2_kernel<<<2048, 256>>>(bb[b][1], b);                     // z2 + L2 stats
        bn_pool_kernel<<<1024, 64>>>(gb[b][1], beb[b][1], batch, b * 64);
    }

    mlp1_kernel<<<N_GRAPHS, 64>>>(Wf1, bf1);
    mlp_stats_kernel<<<32, 64>>>();
    mlp2_kernel<<<(N_GRAPHS + 63) / 64, 64>>>(gf1, bef1, Wf2, bf2, out);
}